// round 10
// baseline (speedup 1.0000x reference)
#include <cuda_runtime.h>
#include <cstdint>

// Problem shape (dataset-fixed): N=100000 voxels, C=128, K=27 offsets, M=50000 pairs.
#define CCH 128
#define MAXELEM (100000 * 128)

__device__ float d_tmp1[MAXELEM];   // conv1 raw output
__device__ float d_tmp2[MAXELEM];   // conv2 raw output
__device__ float d_t1a[MAXELEM];    // tf32(relu(bn1(tmp1))) (conv2 input)
__device__ float d_part1[148 * 256];
__device__ float d_part2[148 * 256];

#define WSTR 144                    // W tile col stride (floats): 4 q-blocks x 36
#define W_FLOATS (128 * WSTR)       // 18432
#define IDX_INTS (2 * 8 * 128)      // 2 halves x 8 slots x (64 in | 64 out)
#define SMEM_FLOATS (W_FLOATS + IDX_INTS)
#define SMEM_BYTES (SMEM_FLOATS * 4)   // 81920 B

// ---------------- helpers ----------------
__device__ __forceinline__ float tf32r(float x) {
    uint32_t u; asm("cvt.rna.tf32.f32 %0, %1;" : "=r"(u) : "f"(x));
    return __uint_as_float(u);
}
__device__ __forceinline__ uint32_t s2u(const void* p) {
    uint32_t a;
    asm("{ .reg .u64 t; cvta.to.shared.u64 t, %1; cvt.u32.u64 %0, t; }" : "=r"(a) : "l"(p));
    return a;
}
__device__ __forceinline__ void barh(int id) {
    asm volatile("bar.sync %0, 256;" :: "r"(id) : "memory");
}
__device__ __forceinline__ void mma_tf32(float* d, const uint32_t* a, uint32_t b0, uint32_t b1) {
    asm volatile(
        "mma.sync.aligned.m16n8k8.row.col.f32.tf32.tf32.f32 "
        "{%0,%1,%2,%3}, {%4,%5,%6,%7}, {%8,%9}, {%0,%1,%2,%3};"
        : "+f"(d[0]), "+f"(d[1]), "+f"(d[2]), "+f"(d[3])
        : "r"(a[0]), "r"(a[1]), "r"(a[2]), "r"(a[3]), "r"(b0), "r"(b1));
}
__device__ __forceinline__ void red4(float* p, float a, float b, float c, float d) {
    asm volatile("red.global.add.v4.f32 [%0], {%1,%2,%3,%4};"
                 :: "l"(p), "f"(a), "f"(b), "f"(c), "f"(d) : "memory");
}
__device__ __forceinline__ void cpa16(uint32_t dst, const void* src, int sbytes) {
    asm volatile("cp.async.cg.shared.global [%0], [%1], 16, %2;"
                 :: "r"(dst), "l"(src), "r"(sbytes) : "memory");
}

// ---------------------------------------------------------------------------
// persistent fused conv, direct-LDG-A edition:
// No A smem staging. Each warp loads its A fragments straight from global
// (rows via the smem idx ring; 64B per row per k-chunk = 2 full sectors),
// software-pipelined one e-step ahead. W stays in smem (q-permuted, LDS.128
// fragments). Scatter is register-direct red.global.add.v4.
// 512 threads = 2 x 256-thread halves (own idx ring + named barrier) so the
// halves drift out of phase; W reloads (rare) use full __syncthreads.
// ---------------------------------------------------------------------------
template <bool ROUNDA>
__global__ __launch_bounds__(512, 1)
void conv_tc(const float* __restrict__ x, const float* __restrict__ w,
             const int* __restrict__ idx_in, const int* __restrict__ idx_out,
             float* __restrict__ out, int M, int SMT, int TT, int PER)
{
    extern __shared__ float sm[];
    float* Wsm = sm;
    int*   Ism = (int*)(sm + W_FLOATS);
    const int tid = threadIdx.x, lane = tid & 31, warp = tid >> 5;
    const int half = warp >> 3;              // 0 or 1
    const int hwarp = warp & 7;              // warp within half
    const int htid = tid & 255;
    const int barid = 1 + half;

    int t0 = blockIdx.x * PER;
    int t1 = t0 + PER; if (t1 > TT) t1 = TT;
    if (t0 >= t1) return;

    int* Ih = Ism + half * (8 * 128);
    const uint32_t ihu = s2u(Ih);

    // zero idx rings (first-use slots must hold in-bounds indices)
    for (int j = tid; j < IDX_INTS; j += 512) Ism[j] = 0;
    __syncthreads();

    // synchronous preload of idx for t0, t0+1 (this half's 64 rows)
    for (int t = t0; t < t0 + 2 && t < t1; t++) {
        int k = t / SMT, smt = t - k * SMT, m0 = smt * 128 + half * 64;
        int nr = M - m0; if (nr > 64) nr = 64; if (nr < 0) nr = 0;
        int* slot = Ih + (t & 7) * 128;
        if (htid < 64)       slot[htid] = (htid < nr) ? __ldg(idx_in + (size_t)k * M + m0 + htid) : 0;
        else if (htid < 128) slot[htid] = ((htid - 64) < nr) ? __ldg(idx_out + (size_t)k * M + m0 + (htid - 64)) : 0;
    }
    __syncthreads();

    int kcur = -1;
    const int wm = hwarp & 1, wn = hwarp >> 1;   // 2x4 warp grid over 64x128
    const int gr = lane >> 2, tg = lane & 3;
    const bool oddlane = (lane & 1);
    const int r0 = wm * 32 + gr;                 // first of this thread's 4 rows
    const float* bbase0 = Wsm + (wn * 32 + gr) * WSTR + tg * 36;

    for (int i = t0; i < t1; i++) {
        int k = i / SMT, smt = i - k * SMT, m0 = smt * 128 + half * 64;
        int nr = M - m0; if (nr > 64) nr = 64; if (nr < 0) nr = 0;
        const int* slot = Ih + (i & 7) * 128;

        // slot i was filled by the cp.async group committed at iter i-2
        asm volatile("cp.async.wait_group 1;" ::: "memory");
        barh(barid);

        // prefetch idx for tile i+2 into ring slot (i+2)&7 (warp 0 of half)
        {
            int tn = i + 2;
            if (tn < t1 && htid < 32) {
                int k2 = tn / SMT, smt2 = tn - k2 * SMT, m02 = smt2 * 128 + half * 64;
                int nr2 = M - m02; if (nr2 > 64) nr2 = 64; if (nr2 < 0) nr2 = 0;
                int r = (htid & 15) * 4;
                const int* g = (htid < 16) ? (idx_in  + (size_t)k2 * M + m02)
                                           : (idx_out + (size_t)k2 * M + m02);
                uint32_t sdst = ihu + (uint32_t)(((tn & 7) * 128) + ((htid < 16) ? 0 : 64) + r) * 4;
                int nb = (r + 4 <= nr2) ? 16 : ((r < nr2) ? (nr2 - r) * 4 : 0);
                cpa16(sdst, g + r, nb);
            }
            asm volatile("cp.async.commit_group;" ::: "memory");
        }

        if (k != kcur) {                       // rare: both halves at same i
            __syncthreads();
            const float* wk = w + (size_t)k * (CCH * CCH);
            #pragma unroll 4
            for (int j = 0; j < 32; j++) {
                int idx = tid + j * 512;
                int cin = idx >> 7, cout = idx & 127;
                Wsm[cout * WSTR + (cin & 3) * 36 + (cin >> 2)] = tf32r(wk[idx]);
            }
            kcur = k;
            __syncthreads();
        }

        // this thread's 4 A-row pointers (rows r0, +8, +16, +24)
        const float* p0 = x + (size_t)slot[r0]      * CCH + tg;
        const float* p1 = x + (size_t)slot[r0 + 8]  * CCH + tg;
        const float* p2 = x + (size_t)slot[r0 + 16] * CCH + tg;
        const float* p3 = x + (size_t)slot[r0 + 24] * CCH + tg;

        float acc[2][4][4];
        #pragma unroll
        for (int a = 0; a < 2; a++)
            #pragma unroll
            for (int b = 0; b < 4; b++)
                #pragma unroll
                for (int c = 0; c < 4; c++) acc[a][b][c] = 0.f;

        // A fragment regs, double-buffered over e: f[buf][q*4 + j], j=row
        float f[2][16];
        #pragma unroll
        for (int q = 0; q < 4; q++) {
            int off = q * 4;
            float v0 = __ldg(p0 + off), v1 = __ldg(p1 + off),
                  v2 = __ldg(p2 + off), v3 = __ldg(p3 + off);
            if (ROUNDA) { v0 = tf32r(v0); v1 = tf32r(v1); v2 = tf32r(v2); v3 = tf32r(v3); }
            f[0][q * 4 + 0] = v0; f[0][q * 4 + 1] = v1;
            f[0][q * 4 + 2] = v2; f[0][q * 4 + 3] = v3;
        }

        #pragma unroll
        for (int e = 0; e < 8; e++) {
            if (e < 7) {
                float* fb = f[(e + 1) & 1];
                #pragma unroll
                for (int q = 0; q < 4; q++) {
                    int off = (e + 1) * 16 + q * 4;
                    float v0 = __ldg(p0 + off), v1 = __ldg(p1 + off),
                          v2 = __ldg(p2 + off), v3 = __ldg(p3 + off);
                    if (ROUNDA) { v0 = tf32r(v0); v1 = tf32r(v1); v2 = tf32r(v2); v3 = tf32r(v3); }
                    fb[q * 4 + 0] = v0; fb[q * 4 + 1] = v1;
                    fb[q * 4 + 2] = v2; fb[q * 4 + 3] = v3;
                }
            }
            float4 bq[4];
            #pragma unroll
            for (int nf = 0; nf < 4; nf++)
                bq[nf] = *reinterpret_cast<const float4*>(bbase0 + nf * 8 * WSTR + e * 4);
            const float* fb = f[e & 1];
            #pragma unroll
            for (int v = 0; v < 2; v++) {
                uint32_t afr[2][4];
                #pragma unroll
                for (int mf = 0; mf < 2; mf++) {
                    afr[mf][0] = __float_as_uint(fb[(2 * v) * 4 + 2 * mf]);
                    afr[mf][1] = __float_as_uint(fb[(2 * v) * 4 + 2 * mf + 1]);
                    afr[mf][2] = __float_as_uint(fb[(2 * v + 1) * 4 + 2 * mf]);
                    afr[mf][3] = __float_as_uint(fb[(2 * v + 1) * 4 + 2 * mf + 1]);
                }
                #pragma unroll
                for (int mf = 0; mf < 2; mf++)
                    #pragma unroll
                    for (int nf = 0; nf < 4; nf++) {
                        uint32_t b0 = __float_as_uint(v ? bq[nf].z : bq[nf].x);
                        uint32_t b1 = __float_as_uint(v ? bq[nf].w : bq[nf].y);
                        mma_tf32(acc[mf][nf], afr[mf], b0, b1);
                    }
            }
        }

        // lane-balanced register-direct scatter
        const int* oslot = slot + 64;
        #pragma unroll
        for (int mf = 0; mf < 2; mf++) {
            #pragma unroll
            for (int rh = 0; rh < 2; rh++) {
                int r = wm * 32 + mf * 16 + rh * 8 + gr;
                int dst = (r < nr) ? oslot[r] : -1;
                #pragma unroll
                for (int nf = 0; nf < 4; nf++) {
                    float c0 = acc[mf][nf][rh * 2 + 0];
                    float c1 = acc[mf][nf][rh * 2 + 1];
                    float q0 = __shfl_xor_sync(0xFFFFFFFFu, c0, 1);
                    float q1 = __shfl_xor_sync(0xFFFFFFFFu, c1, 1);
                    bool mine = (((nf & 1) ^ (lane & 1)) == 0);
                    if (mine && dst >= 0) {
                        float a0 = oddlane ? q0 : c0, a1 = oddlane ? q1 : c1;
                        float a2 = oddlane ? c0 : q0, a3 = oddlane ? c1 : q1;
                        int col = wn * 32 + nf * 8 + (tg & 2) * 2;
                        red4(out + (size_t)dst * CCH + col, a0, a1, a2, a3);
                    }
                }
            }
        }
    }
}

// ---------------- BN stats: per-block partials (no atomics) ----------------
__global__ void bn_stats(const float* __restrict__ t, int N, float* __restrict__ part)
{
    __shared__ float sh[512], sh2[512];
    const int c    = threadIdx.x & 127;
    const int quad = threadIdx.x >> 7;
    float s = 0.f, s2 = 0.f;
    for (int r = blockIdx.x * 4 + quad; r < N; r += gridDim.x * 4) {
        float v = t[r * CCH + c];
        s += v;
        s2 = fmaf(v, v, s2);
    }
    sh[threadIdx.x] = s; sh2[threadIdx.x] = s2;
    __syncthreads();
    if (threadIdx.x < 128) {
        float ss  = sh[c]  + sh[c + 128]  + sh[c + 256]  + sh[c + 384];
        float ss2 = sh2[c] + sh2[c + 128] + sh2[c + 256] + sh2[c + 384];
        part[blockIdx.x * 256 + c]       = ss;
        part[blockIdx.x * 256 + 128 + c] = ss2;
    }
}

__device__ __forceinline__ void make_sb(const float* __restrict__ part,
                                        const float* __restrict__ gamma,
                                        const float* __restrict__ beta,
                                        float invN, float* sb)
{
    if (threadIdx.x < 128) {
        int c = threadIdx.x;
        float s = 0.f, s2 = 0.f;
        #pragma unroll 4
        for (int b = 0; b < 148; b++) {
            s  += part[b * 256 + c];
            s2 += part[b * 256 + 128 + c];
        }
        float mean = s * invN;
        float var  = s2 * invN - mean * mean;
        float sc   = gamma[c] * rsqrtf(var + 1e-5f);
        sb[c]       = sc;
        sb[128 + c] = beta[c] - mean * sc;
    }
    __syncthreads();
}

// bn1 + relu + tf32-round (finalize fused)
__global__ void bn_apply(const float* __restrict__ t, const float* __restrict__ part,
                         const float* __restrict__ gamma, const float* __restrict__ beta,
                         float* __restrict__ o, int total4, float invN)
{
    __shared__ float sb[256];
    make_sb(part, gamma, beta, invN, sb);
    for (int i = blockIdx.x * blockDim.x + threadIdx.x; i < total4; i += gridDim.x * blockDim.x) {
        float4 v = reinterpret_cast<const float4*>(t)[i];
        int c = (i & 31) * 4;
        v.x = tf32r(fmaxf(fmaf(v.x, sb[c + 0], sb[128 + c + 0]), 0.f));
        v.y = tf32r(fmaxf(fmaf(v.y, sb[c + 1], sb[128 + c + 1]), 0.f));
        v.z = tf32r(fmaxf(fmaf(v.z, sb[c + 2], sb[128 + c + 2]), 0.f));
        v.w = tf32r(fmaxf(fmaf(v.w, sb[c + 3], sb[128 + c + 3]), 0.f));
        reinterpret_cast<float4*>(o)[i] = v;
    }
}

// out = relu(bn2(conv2) + identity)  (finalize fused)
__global__ void final_kernel(const float* __restrict__ t2, const float* __restrict__ x,
                             const float* __restrict__ part,
                             const float* __restrict__ gamma, const float* __restrict__ beta,
                             float* __restrict__ out, int total4, float invN)
{
    __shared__ float sb[256];
    make_sb(part, gamma, beta, invN, sb);
    for (int i = blockIdx.x * blockDim.x + threadIdx.x; i < total4; i += gridDim.x * blockDim.x) {
        float4 v  = reinterpret_cast<const float4*>(t2)[i];
        float4 xi = reinterpret_cast<const float4*>(x)[i];
        int c = (i & 31) * 4;
        float4 o;
        o.x = fmaxf(fmaf(v.x, sb[c + 0], sb[128 + c + 0]) + xi.x, 0.f);
        o.y = fmaxf(fmaf(v.y, sb[c + 1], sb[128 + c + 1]) + xi.y, 0.f);
        o.z = fmaxf(fmaf(v.z, sb[c + 2], sb[128 + c + 2]) + xi.z, 0.f);
        o.w = fmaxf(fmaf(v.w, sb[c + 3], sb[128 + c + 3]) + xi.w, 0.f);
        reinterpret_cast<float4*>(out)[i] = o;
    }
}

// ---------------- launch ----------------
extern "C" void kernel_launch(void* const* d_in, const int* in_sizes, int n_in,
                              void* d_out, int out_size)
{
    const float* x      = (const float*)d_in[0];
    const float* w1     = (const float*)d_in[1];
    const float* gamma1 = (const float*)d_in[2];
    const float* beta1  = (const float*)d_in[3];
    const float* w2     = (const float*)d_in[4];
    const float* gamma2 = (const float*)d_in[5];
    const float* beta2  = (const float*)d_in[6];
    const int*   idx_in  = (const int*)d_in[7];
    const int*   idx_out = (const int*)d_in[8];
    float* out = (float*)d_out;

    const int N = in_sizes[0] / CCH;           // 100000
    const int K = in_sizes[1] / (CCH * CCH);   // 27
    const int M = in_sizes[7] / K;             // 50000
    const int SMT = (M + 127) / 128;           // 128-row super-tiles per offset
    const int TT = K * SMT;                    // total super-tiles
    const int GRID = 148;
    const int PER = (TT + GRID - 1) / GRID;

    cudaStream_t s = 0;

    float *tmp1, *tmp2, *t1a, *part1, *part2;
    cudaGetSymbolAddress((void**)&tmp1,  d_tmp1);
    cudaGetSymbolAddress((void**)&tmp2,  d_tmp2);
    cudaGetSymbolAddress((void**)&t1a,   d_t1a);
    cudaGetSymbolAddress((void**)&part1, d_part1);
    cudaGetSymbolAddress((void**)&part2, d_part2);

    size_t nb = (size_t)N * CCH * sizeof(float);
    cudaMemsetAsync(tmp1, 0, nb, s);
    cudaMemsetAsync(tmp2, 0, nb, s);

    cudaFuncSetAttribute(conv_tc<true>,  cudaFuncAttributeMaxDynamicSharedMemorySize, SMEM_BYTES);
    cudaFuncSetAttribute(conv_tc<false>, cudaFuncAttributeMaxDynamicSharedMemorySize, SMEM_BYTES);

    const int total4 = N * (CCH / 4);
    const float invN = 1.0f / (float)N;

    // conv1 (A rounded at fragment load) -> BN1 partials -> fused apply
    conv_tc<true><<<GRID, 512, SMEM_BYTES, s>>>(x, w1, idx_in, idx_out, tmp1, M, SMT, TT, PER);
    bn_stats<<<148, 512, 0, s>>>(tmp1, N, part1);
    bn_apply<<<148, 256, 0, s>>>(tmp1, part1, gamma1, beta1, t1a, total4, invN);

    // conv2 -> BN2 partials -> fused residual epilogue
    conv_tc<false><<<GRID, 512, SMEM_BYTES, s>>>(t1a, w2, idx_in, idx_out, tmp2, M, SMT, TT, PER);
    bn_stats<<<148, 512, 0, s>>>(tmp2, N, part2);
    final_kernel<<<148, 256, 0, s>>>(tmp2, x, part2, gamma2, beta2, out, total4, invN);
}

// round 11
// speedup vs baseline: 2.2699x; 2.2699x over previous
#include <cuda_runtime.h>
#include <cstdint>

// Problem shape (dataset-fixed): N=100000 voxels, C=128, K=27 offsets, M=50000 pairs.
#define CCH 128
#define MAXELEM (100000 * 128)

__device__ float d_tmp[2 * MAXELEM];  // [0]=conv1 raw out, [MAXELEM]=conv2 raw out
__device__ float d_t1a[MAXELEM];      // tf32(relu(bn1(tmp1))) (conv2 input)
__device__ float d_part1[148 * 256];
__device__ float d_part2[148 * 256];

#define AS 132                      // A tile row stride (floats)
#define WSTR 144                    // W tile col stride (floats)
#define A64_FLOATS (64 * AS)        // one 64-row half-tile buffer
#define W_FLOATS (128 * WSTR)
#define W_OFF   (4 * A64_FLOATS)
#define IDX_OFF (W_OFF + W_FLOATS)
#define SMEM_FLOATS (IDX_OFF + 2 * 8 * 128)
#define SMEM_BYTES (SMEM_FLOATS * 4)   // 217088 B

// ---------------- helpers ----------------
__device__ __forceinline__ float tf32r(float x) {
    uint32_t u; asm("cvt.rna.tf32.f32 %0, %1;" : "=r"(u) : "f"(x));
    return __uint_as_float(u);
}
__device__ __forceinline__ uint32_t tf32ru(float x) {
    uint32_t u; asm("cvt.rna.tf32.f32 %0, %1;" : "=r"(u) : "f"(x));
    return u;
}
__device__ __forceinline__ uint32_t s2u(const void* p) {
    uint32_t a;
    asm("{ .reg .u64 t; cvta.to.shared.u64 t, %1; cvt.u32.u64 %0, t; }" : "=r"(a) : "l"(p));
    return a;
}
__device__ __forceinline__ void barh(int id) {
    asm volatile("bar.sync %0, 256;" :: "r"(id) : "memory");
}
__device__ __forceinline__ void mma_tf32(float* d, const uint32_t* a, uint32_t b0, uint32_t b1) {
    asm volatile(
        "mma.sync.aligned.m16n8k8.row.col.f32.tf32.tf32.f32 "
        "{%0,%1,%2,%3}, {%4,%5,%6,%7}, {%8,%9}, {%0,%1,%2,%3};"
        : "+f"(d[0]), "+f"(d[1]), "+f"(d[2]), "+f"(d[3])
        : "r"(a[0]), "r"(a[1]), "r"(a[2]), "r"(a[3]), "r"(b0), "r"(b1));
}
__device__ __forceinline__ void red4(float* p, float a, float b, float c, float d) {
    asm volatile("red.global.add.v4.f32 [%0], {%1,%2,%3,%4};"
                 :: "l"(p), "f"(a), "f"(b), "f"(c), "f"(d) : "memory");
}
__device__ __forceinline__ void cpa16(uint32_t dst, const void* src, int sbytes) {
    asm volatile("cp.async.cg.shared.global [%0], [%1], 16, %2;"
                 :: "r"(dst), "l"(src), "r"(sbytes) : "memory");
}

// ---------------------------------------------------------------------------
// persistent fused conv, split-block edition (R8 best-known config):
// 512 threads = 2 independent 256-thread halves; per half: double-buffered
// 64x132 A tiles filled by cp.async, 8-slot idx ring, named barrier. W shared
// (q-permuted, LDS.128 fragments). tf32 mma, register-direct red.global.v4
// scatter, lane-balanced.
// ---------------------------------------------------------------------------
template <bool ROUNDA>
__global__ __launch_bounds__(512, 1)
void conv_tc(const float* __restrict__ x, const float* __restrict__ w,
             const int* __restrict__ idx_in, const int* __restrict__ idx_out,
             float* __restrict__ out, int M, int SMT, int TT, int PER)
{
    extern __shared__ float sm[];
    float* Wsm = sm + W_OFF;
    int*   Ism = (int*)(sm + IDX_OFF);
    const int tid = threadIdx.x, lane = tid & 31, warp = tid >> 5;
    const int half = warp >> 3;
    const int hwarp = warp & 7;
    const int htid = tid & 255;
    const int barid = 1 + half;

    int t0 = blockIdx.x * PER;
    int t1 = t0 + PER; if (t1 > TT) t1 = TT;
    if (t0 >= t1) return;

    float* Ah = sm + half * (2 * A64_FLOATS);
    int*   Ih = Ism + half * (8 * 128);
    const uint32_t ahu = s2u(Ah);
    const uint32_t ihu = s2u(Ih);

    for (int t = t0; t < t0 + 2 && t < t1; t++) {
        int k = t / SMT, smt = t - k * SMT, m0 = smt * 128 + half * 64;
        int nr = M - m0; if (nr > 64) nr = 64; if (nr < 0) nr = 0;
        int* slot = Ih + (t & 7) * 128;
        if (htid < 64)       slot[htid] = (htid < nr) ? __ldg(idx_in + (size_t)k * M + m0 + htid) : 0;
        else if (htid < 128) slot[htid] = ((htid - 64) < nr) ? __ldg(idx_out + (size_t)k * M + m0 + (htid - 64)) : 0;
    }
    __syncthreads();

    auto issue_gather = [&](int t) {
        int k = t / SMT, smt = t - k * SMT, m0 = smt * 128 + half * 64;
        int nr = M - m0; if (nr > 64) nr = 64; if (nr < 0) nr = 0;
        const int* slot = Ih + (t & 7) * 128;
        uint32_t ab = ahu + (uint32_t)(t & 1) * (A64_FLOATS * 4);
        #pragma unroll
        for (int j = 0; j < 8; j++) {
            int id = htid + j * 256;
            int row = id >> 5, seg = id & 31;
            int ok = (row < nr);
            int src = ok ? slot[row] : 0;
            cpa16(ab + (uint32_t)(row * AS + seg * 4) * 4,
                  x + (size_t)src * CCH + seg * 4, ok ? 16 : 0);
        }
        int tn = t + 2;
        if (tn < t1 && htid < 32) {
            int k2 = tn / SMT, smt2 = tn - k2 * SMT, m02 = smt2 * 128 + half * 64;
            int nr2 = M - m02; if (nr2 > 64) nr2 = 64; if (nr2 < 0) nr2 = 0;
            int r = (htid & 15) * 4;
            const int* g = (htid < 16) ? (idx_in  + (size_t)k2 * M + m02)
                                       : (idx_out + (size_t)k2 * M + m02);
            uint32_t sdst = ihu + (uint32_t)(((tn & 7) * 128) + ((htid < 16) ? 0 : 64) + r) * 4;
            int nb = (r + 4 <= nr2) ? 16 : ((r < nr2) ? (nr2 - r) * 4 : 0);
            cpa16(sdst, g + r, nb);
        }
        asm volatile("cp.async.commit_group;" ::: "memory");
    };

    issue_gather(t0);
    if (t0 + 1 < t1) issue_gather(t0 + 1);

    int kcur = -1;
    const int wm = hwarp & 1, wn = hwarp >> 1;
    const int gr = lane >> 2, tg = lane & 3;
    const bool oddlane = (lane & 1);

    for (int i = t0; i < t1; i++) {
        int k = i / SMT, smt = i - k * SMT, m0 = smt * 128 + half * 64;
        int nr = M - m0; if (nr > 64) nr = 64; if (nr < 0) nr = 0;
        const float* Asm = Ah + (i & 1) * A64_FLOATS;
        const int* slot = Ih + (i & 7) * 128;

        if (i + 1 < t1) asm volatile("cp.async.wait_group 1;" ::: "memory");
        else            asm volatile("cp.async.wait_group 0;" ::: "memory");
        barh(barid);

        if (k != kcur) {
            __syncthreads();
            const float* wk = w + (size_t)k * (CCH * CCH);
            #pragma unroll 4
            for (int j = 0; j < 32; j++) {
                int idx = tid + j * 512;
                int cin = idx >> 7, cout = idx & 127;
                Wsm[cout * WSTR + (cin & 3) * 36 + (cin >> 2)] = tf32r(wk[idx]);
            }
            kcur = k;
            __syncthreads();
        }

        float acc[2][4][4];
        #pragma unroll
        for (int a = 0; a < 2; a++)
            #pragma unroll
            for (int b = 0; b < 4; b++)
                #pragma unroll
                for (int c = 0; c < 4; c++) acc[a][b][c] = 0.f;

        const float* arow0 = Asm + (wm * 32 + gr) * AS;

        #pragma unroll
        for (int u = 0; u < 8; u++) {
            float4 bq[4];
            #pragma unroll
            for (int nf = 0; nf < 4; nf++)
                bq[nf] = *reinterpret_cast<const float4*>(
                    Wsm + (wn * 32 + nf * 8 + gr) * WSTR + tg * 36 + u * 4);
            #pragma unroll
            for (int v = 0; v < 2; v++) {
                int kk = (2 * u + v) * 8;
                uint32_t afr[2][4];
                #pragma unroll
                for (int mf = 0; mf < 2; mf++) {
                    const float* ap = arow0 + mf * 16 * AS + kk + tg;
                    if (ROUNDA) {
                        afr[mf][0] = tf32ru(ap[0]);
                        afr[mf][1] = tf32ru(ap[8 * AS]);
                        afr[mf][2] = tf32ru(ap[4]);
                        afr[mf][3] = tf32ru(ap[8 * AS + 4]);
                    } else {
                        afr[mf][0] = __float_as_uint(ap[0]);
                        afr[mf][1] = __float_as_uint(ap[8 * AS]);
                        afr[mf][2] = __float_as_uint(ap[4]);
                        afr[mf][3] = __float_as_uint(ap[8 * AS + 4]);
                    }
                }
                #pragma unroll
                for (int mf = 0; mf < 2; mf++)
                    #pragma unroll
                    for (int nf = 0; nf < 4; nf++) {
                        uint32_t b0 = __float_as_uint(v ? bq[nf].z : bq[nf].x);
                        uint32_t b1 = __float_as_uint(v ? bq[nf].w : bq[nf].y);
                        mma_tf32(acc[mf][nf], afr[mf], b0, b1);
                    }
            }
        }
        barh(barid);                 // this half done reading its A buffer

        if (i + 2 < t1) issue_gather(i + 2);

        const int* oslot = slot + 64;
        #pragma unroll
        for (int mf = 0; mf < 2; mf++) {
            #pragma unroll
            for (int rh = 0; rh < 2; rh++) {
                int r = wm * 32 + mf * 16 + rh * 8 + gr;
                int dst = (r < nr) ? oslot[r] : -1;
                #pragma unroll
                for (int nf = 0; nf < 4; nf++) {
                    float c0 = acc[mf][nf][rh * 2 + 0];
                    float c1 = acc[mf][nf][rh * 2 + 1];
                    float q0 = __shfl_xor_sync(0xFFFFFFFFu, c0, 1);
                    float q1 = __shfl_xor_sync(0xFFFFFFFFu, c1, 1);
                    bool mine = (((nf & 1) ^ (lane & 1)) == 0);
                    if (mine && dst >= 0) {
                        float a0 = oddlane ? q0 : c0, a1 = oddlane ? q1 : c1;
                        float a2 = oddlane ? c0 : q0, a3 = oddlane ? c1 : q1;
                        int col = wn * 32 + nf * 8 + (tg & 2) * 2;
                        red4(out + (size_t)dst * CCH + col, a0, a1, a2, a3);
                    }
                }
            }
        }
    }
}

// ---------------- BN stats: vectorized float4, per-block partials ----------
__global__ __launch_bounds__(512)
void bn_stats(const float* __restrict__ t, int N, float* __restrict__ part)
{
    __shared__ float sh[16 * 128], sh2[16 * 128];
    const int cg = threadIdx.x & 31;       // 32 column chunks of 4 channels
    const int rs = threadIdx.x >> 5;       // 16 row streams
    float4 s  = make_float4(0.f, 0.f, 0.f, 0.f);
    float4 s2 = make_float4(0.f, 0.f, 0.f, 0.f);
    for (int r = blockIdx.x * 16 + rs; r < N; r += gridDim.x * 16) {
        float4 v = reinterpret_cast<const float4*>(t)[(size_t)r * 32 + cg];
        s.x += v.x; s.y += v.y; s.z += v.z; s.w += v.w;
        s2.x = fmaf(v.x, v.x, s2.x); s2.y = fmaf(v.y, v.y, s2.y);
        s2.z = fmaf(v.z, v.z, s2.z); s2.w = fmaf(v.w, v.w, s2.w);
    }
    reinterpret_cast<float4*>(sh)[rs * 32 + cg]  = s;
    reinterpret_cast<float4*>(sh2)[rs * 32 + cg] = s2;
    __syncthreads();
    if (threadIdx.x < 128) {
        int c = threadIdx.x;
        float ss = 0.f, ss2 = 0.f;
        #pragma unroll
        for (int j = 0; j < 16; j++) {
            ss  += sh[j * 128 + c];
            ss2 += sh2[j * 128 + c];
        }
        part[blockIdx.x * 256 + c]       = ss;
        part[blockIdx.x * 256 + 128 + c] = ss2;
    }
}

// reduce partials -> per-channel scale/bias into smem
__device__ __forceinline__ void make_sb(const float* __restrict__ part,
                                        const float* __restrict__ gamma,
                                        const float* __restrict__ beta,
                                        float invN, float* sb)
{
    if (threadIdx.x < 128) {
        int c = threadIdx.x;
        float s = 0.f, s2 = 0.f;
        #pragma unroll 4
        for (int b = 0; b < 148; b++) {
            s  += part[b * 256 + c];
            s2 += part[b * 256 + 128 + c];
        }
        float mean = s * invN;
        float var  = s2 * invN - mean * mean;
        float sc   = gamma[c] * rsqrtf(var + 1e-5f);
        sb[c]       = sc;
        sb[128 + c] = beta[c] - mean * sc;
    }
    __syncthreads();
}

// bn1 + relu + tf32-round (finalize fused)
__global__ __launch_bounds__(512)
void bn_apply(const float* __restrict__ t, const float* __restrict__ part,
              const float* __restrict__ gamma, const float* __restrict__ beta,
              float* __restrict__ o, int total4, float invN)
{
    __shared__ float sb[256];
    make_sb(part, gamma, beta, invN, sb);
    for (int i = blockIdx.x * blockDim.x + threadIdx.x; i < total4; i += gridDim.x * blockDim.x) {
        float4 v = reinterpret_cast<const float4*>(t)[i];
        int c = (i & 31) * 4;
        v.x = tf32r(fmaxf(fmaf(v.x, sb[c + 0], sb[128 + c + 0]), 0.f));
        v.y = tf32r(fmaxf(fmaf(v.y, sb[c + 1], sb[128 + c + 1]), 0.f));
        v.z = tf32r(fmaxf(fmaf(v.z, sb[c + 2], sb[128 + c + 2]), 0.f));
        v.w = tf32r(fmaxf(fmaf(v.w, sb[c + 3], sb[128 + c + 3]), 0.f));
        reinterpret_cast<float4*>(o)[i] = v;
    }
}

// out = relu(bn2(conv2) + identity)  (finalize fused)
__global__ __launch_bounds__(512)
void final_kernel(const float* __restrict__ t2, const float* __restrict__ x,
                  const float* __restrict__ part,
                  const float* __restrict__ gamma, const float* __restrict__ beta,
                  float* __restrict__ out, int total4, float invN)
{
    __shared__ float sb[256];
    make_sb(part, gamma, beta, invN, sb);
    for (int i = blockIdx.x * blockDim.x + threadIdx.x; i < total4; i += gridDim.x * blockDim.x) {
        float4 v  = reinterpret_cast<const float4*>(t2)[i];
        float4 xi = reinterpret_cast<const float4*>(x)[i];
        int c = (i & 31) * 4;
        float4 o;
        o.x = fmaxf(fmaf(v.x, sb[c + 0], sb[128 + c + 0]) + xi.x, 0.f);
        o.y = fmaxf(fmaf(v.y, sb[c + 1], sb[128 + c + 1]) + xi.y, 0.f);
        o.z = fmaxf(fmaf(v.z, sb[c + 2], sb[128 + c + 2]) + xi.z, 0.f);
        o.w = fmaxf(fmaf(v.w, sb[c + 3], sb[128 + c + 3]) + xi.w, 0.f);
        reinterpret_cast<float4*>(out)[i] = o;
    }
}

// ---------------- launch ----------------
extern "C" void kernel_launch(void* const* d_in, const int* in_sizes, int n_in,
                              void* d_out, int out_size)
{
    const float* x      = (const float*)d_in[0];
    const float* w1     = (const float*)d_in[1];
    const float* gamma1 = (const float*)d_in[2];
    const float* beta1  = (const float*)d_in[3];
    const float* w2     = (const float*)d_in[4];
    const float* gamma2 = (const float*)d_in[5];
    const float* beta2  = (const float*)d_in[6];
    const int*   idx_in  = (const int*)d_in[7];
    const int*   idx_out = (const int*)d_in[8];
    float* out = (float*)d_out;

    const int N = in_sizes[0] / CCH;           // 100000
    const int K = in_sizes[1] / (CCH * CCH);   // 27
    const int M = in_sizes[7] / K;             // 50000
    const int SMT = (M + 127) / 128;           // 128-row super-tiles per offset
    const int TT = K * SMT;                    // total super-tiles
    const int GRID = 148;
    const int PER = (TT + GRID - 1) / GRID;

    cudaStream_t s = 0;

    float *tmp, *t1a, *part1, *part2;
    cudaGetSymbolAddress((void**)&tmp,   d_tmp);
    cudaGetSymbolAddress((void**)&t1a,   d_t1a);
    cudaGetSymbolAddress((void**)&part1, d_part1);
    cudaGetSymbolAddress((void**)&part2, d_part2);
    float* tmp1 = tmp;
    float* tmp2 = tmp + (size_t)MAXELEM;

    size_t nb = (size_t)N * CCH * sizeof(float);
    cudaMemsetAsync(tmp1, 0, 2 * nb, s);   // zero both conv outputs in one pass

    cudaFuncSetAttribute(conv_tc<true>,  cudaFuncAttributeMaxDynamicSharedMemorySize, SMEM_BYTES);
    cudaFuncSetAttribute(conv_tc<false>, cudaFuncAttributeMaxDynamicSharedMemorySize, SMEM_BYTES);

    const int total4 = N * (CCH / 4);
    const float invN = 1.0f / (float)N;

    // conv1 (A rounded at fragment load) -> BN1 partials -> fused apply
    conv_tc<true><<<GRID, 512, SMEM_BYTES, s>>>(x, w1, idx_in, idx_out, tmp1, M, SMT, TT, PER);
    bn_stats<<<148, 512, 0, s>>>(tmp1, N, part1);
    bn_apply<<<148, 512, 0, s>>>(tmp1, part1, gamma1, beta1, t1a, total4, invN);

    // conv2 -> BN2 partials -> fused residual epilogue
    conv_tc<false><<<GRID, 512, SMEM_BYTES, s>>>(t1a, w2, idx_in, idx_out, tmp2, M, SMT, TT, PER);
    bn_stats<<<148, 512, 0, s>>>(tmp2, N, part2);
    final_kernel<<<148, 512, 0, s>>>(tmp2, x, part2, gamma2, beta2, out, total4, invN);
}

// round 12
// speedup vs baseline: 2.6338x; 1.1603x over previous
#include <cuda_runtime.h>
#include <cuda_fp16.h>
#include <cstdint>

// Problem shape (dataset-fixed): N=100000 voxels, C=128, K=27 offsets, M=50000 pairs.
#define CCH 128
#define MAXELEM (100000 * 128)

__device__ float    d_tmp[2 * MAXELEM];   // conv1 / conv2 raw fp32 outputs
__device__ uint32_t d_xh[MAXELEM / 2];    // fp16-packed x (conv1 input)
__device__ uint32_t d_t1h[MAXELEM / 2];   // fp16-packed relu(bn1(tmp1)) (conv2 input)
__device__ float    d_part1[148 * 256];
__device__ float    d_part2[148 * 256];

// ---------------- smem layout (bytes) ----------------
// A tiles: 4 buffers (2 per half) of 64 rows x 136 halves (272B/row, 8-half pad)
// W tile: 128 couts x 136 halves. idx rings: 2 halves x 8 slots x 128 ints.
#define AROW_B   272
#define A_TILE_B (64 * AROW_B)             // 17408
#define W_OFF_B  (4 * A_TILE_B)            // 69632
#define W_TILE_B (128 * AROW_B)            // 34816
#define IDX_OFF_B (W_OFF_B + W_TILE_B)     // 104448
#define SMEM_BYTES (IDX_OFF_B + 2 * 8 * 128 * 4)   // 112640

// ---------------- helpers ----------------
__device__ __forceinline__ uint32_t s2u(const void* p) {
    uint32_t a;
    asm("{ .reg .u64 t; cvta.to.shared.u64 t, %1; cvt.u32.u64 %0, t; }" : "=r"(a) : "l"(p));
    return a;
}
__device__ __forceinline__ void barh(int id) {
    asm volatile("bar.sync %0, 256;" :: "r"(id) : "memory");
}
__device__ __forceinline__ void mma_f16(float* d, uint32_t a0, uint32_t a1, uint32_t a2,
                                        uint32_t a3, uint32_t b0, uint32_t b1) {
    asm volatile(
        "mma.sync.aligned.m16n8k16.row.col.f32.f16.f16.f32 "
        "{%0,%1,%2,%3}, {%4,%5,%6,%7}, {%8,%9}, {%0,%1,%2,%3};"
        : "+f"(d[0]), "+f"(d[1]), "+f"(d[2]), "+f"(d[3])
        : "r"(a0), "r"(a1), "r"(a2), "r"(a3), "r"(b0), "r"(b1));
}
__device__ __forceinline__ void red4(float* p, float a, float b, float c, float d) {
    asm volatile("red.global.add.v4.f32 [%0], {%1,%2,%3,%4};"
                 :: "l"(p), "f"(a), "f"(b), "f"(c), "f"(d) : "memory");
}
__device__ __forceinline__ void cpa16(uint32_t dst, const void* src, int sbytes) {
    asm volatile("cp.async.cg.shared.global [%0], [%1], 16, %2;"
                 :: "r"(dst), "l"(src), "r"(sbytes) : "memory");
}
__device__ __forceinline__ uint32_t pack2(float a, float b) {
    __half2 h = __floats2half2_rn(a, b);
    return *reinterpret_cast<uint32_t*>(&h);
}

// ---------------------------------------------------------------------------
// persistent fused conv, fp16-operand edition:
// 512 threads = 2 independent 256-thread halves (named barriers, own idx ring,
// double-buffered 64-row fp16 A tiles via cp.async). W converted to fp16 in
// smem per k-offset. mma.m16n8k16 f16xf16->f32. Register-direct red.global.v4
// scatter (D fragment layout identical to the old tf32 path).
// ---------------------------------------------------------------------------
__global__ __launch_bounds__(512, 1)
void conv_tc(const uint32_t* __restrict__ xh, const float* __restrict__ w,
             const int* __restrict__ idx_in, const int* __restrict__ idx_out,
             float* __restrict__ out, int M, int SMT, int TT, int PER)
{
    extern __shared__ __align__(16) char smc[];
    uint32_t* Ww  = (uint32_t*)(smc + W_OFF_B);   // W word view (2 halves/word)
    __half*   Wh  = (__half*)(smc + W_OFF_B);
    int*      Ism = (int*)(smc + IDX_OFF_B);
    const int tid = threadIdx.x, lane = tid & 31, warp = tid >> 5;
    const int half = warp >> 3;
    const int hwarp = warp & 7;
    const int htid = tid & 255;
    const int barid = 1 + half;

    int t0 = blockIdx.x * PER;
    int t1 = t0 + PER; if (t1 > TT) t1 = TT;
    if (t0 >= t1) return;

    char* Ah = smc + half * (2 * A_TILE_B);
    int*  Ih = Ism + half * (8 * 128);
    const uint32_t ahu = s2u(Ah);
    const uint32_t ihu = s2u(Ih);

    // synchronous preload of idx for t0, t0+1 (this half's 64 rows)
    for (int t = t0; t < t0 + 2 && t < t1; t++) {
        int k = t / SMT, smt = t - k * SMT, m0 = smt * 128 + half * 64;
        int nr = M - m0; if (nr > 64) nr = 64; if (nr < 0) nr = 0;
        int* slot = Ih + (t & 7) * 128;
        if (htid < 64)       slot[htid] = (htid < nr) ? __ldg(idx_in + (size_t)k * M + m0 + htid) : 0;
        else if (htid < 128) slot[htid] = ((htid - 64) < nr) ? __ldg(idx_out + (size_t)k * M + m0 + (htid - 64)) : 0;
    }
    __syncthreads();

    // gather this half's 64 fp16 rows (256B each = 16 chunks) + idx prefetch t+2
    auto issue_gather = [&](int t) {
        int k = t / SMT, smt = t - k * SMT, m0 = smt * 128 + half * 64;
        int nr = M - m0; if (nr > 64) nr = 64; if (nr < 0) nr = 0;
        const int* slot = Ih + (t & 7) * 128;
        uint32_t ab = ahu + (uint32_t)(t & 1) * A_TILE_B;
        #pragma unroll
        for (int j = 0; j < 4; j++) {
            int id = htid + j * 256;
            int row = id >> 4, s = id & 15;
            int ok = (row < nr);
            int src = ok ? slot[row] : 0;
            cpa16(ab + (uint32_t)(row * AROW_B + s * 16),
                  (const char*)xh + (size_t)src * 256 + s * 16, ok ? 16 : 0);
        }
        int tn = t + 2;
        if (tn < t1 && htid < 32) {
            int k2 = tn / SMT, smt2 = tn - k2 * SMT, m02 = smt2 * 128 + half * 64;
            int nr2 = M - m02; if (nr2 > 64) nr2 = 64; if (nr2 < 0) nr2 = 0;
            int r = (htid & 15) * 4;
            const int* g = (htid < 16) ? (idx_in  + (size_t)k2 * M + m02)
                                       : (idx_out + (size_t)k2 * M + m02);
            uint32_t sdst = ihu + (uint32_t)(((tn & 7) * 128) + ((htid < 16) ? 0 : 64) + r) * 4;
            int nb = (r + 4 <= nr2) ? 16 : ((r < nr2) ? (nr2 - r) * 4 : 0);
            cpa16(sdst, g + r, nb);
        }
        asm volatile("cp.async.commit_group;" ::: "memory");
    };

    issue_gather(t0);
    if (t0 + 1 < t1) issue_gather(t0 + 1);

    int kcur = -1;
    const int wm = hwarp & 1, wn = hwarp >> 1;   // 2x4 warp grid over 64x128
    const int gr = lane >> 2, tg = lane & 3;
    const bool oddlane = (lane & 1);

    for (int i = t0; i < t1; i++) {
        int k = i / SMT, smt = i - k * SMT, m0 = smt * 128 + half * 64;
        int nr = M - m0; if (nr > 64) nr = 64; if (nr < 0) nr = 0;
        const uint32_t* Aw = (const uint32_t*)(Ah + (i & 1) * A_TILE_B);
        const int* slot = Ih + (i & 7) * 128;

        if (i + 1 < t1) asm volatile("cp.async.wait_group 1;" ::: "memory");
        else            asm volatile("cp.async.wait_group 0;" ::: "memory");
        barh(barid);

        if (k != kcur) {                       // rare: both halves at same i
            __syncthreads();
            const float* wk = w + (size_t)k * (CCH * CCH);
            #pragma unroll 4
            for (int j = 0; j < 32; j++) {
                int idx = tid + j * 512;
                int cin = idx >> 7, cout = idx & 127;
                Wh[cout * 136 + cin] = __float2half_rn(wk[idx]);
            }
            kcur = k;
            __syncthreads();
        }

        float acc[2][4][4];
        #pragma unroll
        for (int a = 0; a < 2; a++)
            #pragma unroll
            for (int b = 0; b < 4; b++)
                #pragma unroll
                for (int c = 0; c < 4; c++) acc[a][b][c] = 0.f;

        const int rbase = wm * 32 + gr;        // row word stride = 68

        #pragma unroll
        for (int ks = 0; ks < 8; ks++) {
            uint32_t b0[4], b1[4];
            #pragma unroll
            for (int nf = 0; nf < 4; nf++) {
                int col = wn * 32 + nf * 8 + gr;
                b0[nf] = Ww[col * 68 + ks * 8 + tg];
                b1[nf] = Ww[col * 68 + ks * 8 + tg + 4];
            }
            #pragma unroll
            for (int mf = 0; mf < 2; mf++) {
                int r = rbase + mf * 16;
                uint32_t a0 = Aw[r * 68 + ks * 8 + tg];
                uint32_t a1 = Aw[(r + 8) * 68 + ks * 8 + tg];
                uint32_t a2 = Aw[r * 68 + ks * 8 + tg + 4];
                uint32_t a3 = Aw[(r + 8) * 68 + ks * 8 + tg + 4];
                #pragma unroll
                for (int nf = 0; nf < 4; nf++)
                    mma_f16(acc[mf][nf], a0, a1, a2, a3, b0[nf], b1[nf]);
            }
        }
        barh(barid);                 // this half done reading its A buffer

        if (i + 2 < t1) issue_gather(i + 2);

        // lane-balanced register-direct scatter (D layout same as tf32 path)
        const int* oslot = slot + 64;
        #pragma unroll
        for (int mf = 0; mf < 2; mf++) {
            #pragma unroll
            for (int rh = 0; rh < 2; rh++) {
                int r = wm * 32 + mf * 16 + rh * 8 + gr;
                int dst = (r < nr) ? oslot[r] : -1;
                #pragma unroll
                for (int nf = 0; nf < 4; nf++) {
                    float c0 = acc[mf][nf][rh * 2 + 0];
                    float c1 = acc[mf][nf][rh * 2 + 1];
                    float q0 = __shfl_xor_sync(0xFFFFFFFFu, c0, 1);
                    float q1 = __shfl_xor_sync(0xFFFFFFFFu, c1, 1);
                    bool mine = (((nf & 1) ^ (lane & 1)) == 0);
                    if (mine && dst >= 0) {
                        float a0 = oddlane ? q0 : c0, a1 = oddlane ? q1 : c1;
                        float a2 = oddlane ? c0 : q0, a3 = oddlane ? c1 : q1;
                        int col = wn * 32 + nf * 8 + (tg & 2) * 2;
                        red4(out + (size_t)dst * CCH + col, a0, a1, a2, a3);
                    }
                }
            }
        }
    }
}

// ---------------- pack x -> fp16 (natural channel order) ----------------
__global__ __launch_bounds__(512)
void pack_x(const float* __restrict__ x, uint32_t* __restrict__ xh, int total32)
{
    for (int i = blockIdx.x * blockDim.x + threadIdx.x; i < total32;
         i += gridDim.x * blockDim.x) {
        float4 v = reinterpret_cast<const float4*>(x)[i];
        reinterpret_cast<uint2*>(xh)[i] = make_uint2(pack2(v.x, v.y), pack2(v.z, v.w));
    }
}

// ---------------- BN stats: vectorized float4, per-block partials ----------
__global__ __launch_bounds__(512)
void bn_stats(const float* __restrict__ t, int N, float* __restrict__ part)
{
    __shared__ float sh[16 * 128], sh2[16 * 128];
    const int cg = threadIdx.x & 31;
    const int rs = threadIdx.x >> 5;
    float4 s  = make_float4(0.f, 0.f, 0.f, 0.f);
    float4 s2 = make_float4(0.f, 0.f, 0.f, 0.f);
    for (int r = blockIdx.x * 16 + rs; r < N; r += gridDim.x * 16) {
        float4 v = reinterpret_cast<const float4*>(t)[(size_t)r * 32 + cg];
        s.x += v.x; s.y += v.y; s.z += v.z; s.w += v.w;
        s2.x = fmaf(v.x, v.x, s2.x); s2.y = fmaf(v.y, v.y, s2.y);
        s2.z = fmaf(v.z, v.z, s2.z); s2.w = fmaf(v.w, v.w, s2.w);
    }
    reinterpret_cast<float4*>(sh)[rs * 32 + cg]  = s;
    reinterpret_cast<float4*>(sh2)[rs * 32 + cg] = s2;
    __syncthreads();
    if (threadIdx.x < 128) {
        int c = threadIdx.x;
        float ss = 0.f, ss2 = 0.f;
        #pragma unroll
        for (int j = 0; j < 16; j++) {
            ss  += sh[j * 128 + c];
            ss2 += sh2[j * 128 + c];
        }
        part[blockIdx.x * 256 + c]       = ss;
        part[blockIdx.x * 256 + 128 + c] = ss2;
    }
}

__device__ __forceinline__ void make_sb(const float* __restrict__ part,
                                        const float* __restrict__ gamma,
                                        const float* __restrict__ beta,
                                        float invN, float* sb)
{
    if (threadIdx.x < 128) {
        int c = threadIdx.x;
        float s = 0.f, s2 = 0.f;
        #pragma unroll 4
        for (int b = 0; b < 148; b++) {
            s  += part[b * 256 + c];
            s2 += part[b * 256 + 128 + c];
        }
        float mean = s * invN;
        float var  = s2 * invN - mean * mean;
        float sc   = gamma[c] * rsqrtf(var + 1e-5f);
        sb[c]       = sc;
        sb[128 + c] = beta[c] - mean * sc;
    }
    __syncthreads();
}

// bn1 + relu -> fp16 packed (conv2 input)
__global__ __launch_bounds__(512)
void bn_apply(const float* __restrict__ t, const float* __restrict__ part,
              const float* __restrict__ gamma, const float* __restrict__ beta,
              uint32_t* __restrict__ o, int total32, float invN)
{
    __shared__ float sb[256];
    make_sb(part, gamma, beta, invN, sb);
    for (int i = blockIdx.x * blockDim.x + threadIdx.x; i < total32;
         i += gridDim.x * blockDim.x) {
        float4 v = reinterpret_cast<const float4*>(t)[i];
        int c = (i & 31) * 4;
        v.x = fmaxf(fmaf(v.x, sb[c + 0], sb[128 + c + 0]), 0.f);
        v.y = fmaxf(fmaf(v.y, sb[c + 1], sb[128 + c + 1]), 0.f);
        v.z = fmaxf(fmaf(v.z, sb[c + 2], sb[128 + c + 2]), 0.f);
        v.w = fmaxf(fmaf(v.w, sb[c + 3], sb[128 + c + 3]), 0.f);
        reinterpret_cast<uint2*>(o)[i] = make_uint2(pack2(v.x, v.y), pack2(v.z, v.w));
    }
}

// out = relu(bn2(conv2) + identity)
__global__ __launch_bounds__(512)
void final_kernel(const float* __restrict__ t2, const float* __restrict__ x,
                  const float* __restrict__ part,
                  const float* __restrict__ gamma, const float* __restrict__ beta,
                  float* __restrict__ out, int total4, float invN)
{
    __shared__ float sb[256];
    make_sb(part, gamma, beta, invN, sb);
    for (int i = blockIdx.x * blockDim.x + threadIdx.x; i < total4;
         i += gridDim.x * blockDim.x) {
        float4 v  = reinterpret_cast<const float4*>(t2)[i];
        float4 xi = reinterpret_cast<const float4*>(x)[i];
        int c = (i & 31) * 4;
        float4 o;
        o.x = fmaxf(fmaf(v.x, sb[c + 0], sb[128 + c + 0]) + xi.x, 0.f);
        o.y = fmaxf(fmaf(v.y, sb[c + 1], sb[128 + c + 1]) + xi.y, 0.f);
        o.z = fmaxf(fmaf(v.z, sb[c + 2], sb[128 + c + 2]) + xi.z, 0.f);
        o.w = fmaxf(fmaf(v.w, sb[c + 3], sb[128 + c + 3]) + xi.w, 0.f);
        reinterpret_cast<float4*>(out)[i] = o;
    }
}

// ---------------- launch ----------------
extern "C" void kernel_launch(void* const* d_in, const int* in_sizes, int n_in,
                              void* d_out, int out_size)
{
    const float* x      = (const float*)d_in[0];
    const float* w1     = (const float*)d_in[1];
    const float* gamma1 = (const float*)d_in[2];
    const float* beta1  = (const float*)d_in[3];
    const float* w2     = (const float*)d_in[4];
    const float* gamma2 = (const float*)d_in[5];
    const float* beta2  = (const float*)d_in[6];
    const int*   idx_in  = (const int*)d_in[7];
    const int*   idx_out = (const int*)d_in[8];
    float* out = (float*)d_out;

    const int N = in_sizes[0] / CCH;           // 100000
    const int K = in_sizes[1] / (CCH * CCH);   // 27
    const int M = in_sizes[7] / K;             // 50000
    const int SMT = (M + 127) / 128;           // 128-row super-tiles per offset
    const int TT = K * SMT;                    // total super-tiles
    const int GRID = 148;
    const int PER = (TT + GRID - 1) / GRID;

    cudaStream_t s = 0;

    float *tmp, *part1, *part2;
    uint32_t *xh, *t1h;
    cudaGetSymbolAddress((void**)&tmp,   d_tmp);
    cudaGetSymbolAddress((void**)&xh,    d_xh);
    cudaGetSymbolAddress((void**)&t1h,   d_t1h);
    cudaGetSymbolAddress((void**)&part1, d_part1);
    cudaGetSymbolAddress((void**)&part2, d_part2);
    float* tmp1 = tmp;
    float* tmp2 = tmp + (size_t)MAXELEM;

    size_t nb = (size_t)N * CCH * sizeof(float);
    cudaMemsetAsync(tmp1, 0, 2 * nb, s);

    cudaFuncSetAttribute(conv_tc, cudaFuncAttributeMaxDynamicSharedMemorySize, SMEM_BYTES);

    const int total4 = N * (CCH / 4);
    const int total32 = N * 32;                // float4 groups per row count
    const float invN = 1.0f / (float)N;

    // pack x -> fp16
    pack_x<<<296, 512, 0, s>>>(x, xh, total32);

    // conv1 -> BN1 partials -> fused BN+ReLU+fp16 pack
    conv_tc<<<GRID, 512, SMEM_BYTES, s>>>(xh, w1, idx_in, idx_out, tmp1, M, SMT, TT, PER);
    bn_stats<<<148, 512, 0, s>>>(tmp1, N, part1);
    bn_apply<<<296, 512, 0, s>>>(tmp1, part1, gamma1, beta1, t1h, total32, invN);

    // conv2 -> BN2 partials -> fused residual epilogue
    conv_tc<<<GRID, 512, SMEM_BYTES, s>>>(t1h, w2, idx_in, idx_out, tmp2, M, SMT, TT, PER);
    bn_stats<<<148, 512, 0, s>>>(tmp2, N, part2);
    final_kernel<<<296, 512, 0, s>>>(tmp2, x, part2, gamma2, beta2, out, total4, invN);
}